// round 15
// baseline (speedup 1.0000x reference)
#include <cuda_runtime.h>
#include <cuda_fp16.h>
#include <cstddef>
#include <cstdint>

#define BB 1024   // batch
#define TT 512    // time steps
#define II 64     // input dim
#define HH 256    // hidden dim
#define G4 1024   // 4*H
#define NBLK 256  // 16 m-tiles x 16 slices (2 CTAs/SM)
#define KC0 (II + HH)    // 320
#define KC1 (HH + HH)    // 512
#define KB0 (KC0 / 16)   // 20
#define KB1 (KC1 / 16)   // 32

// ---- smem layout (bytes) ----
#define SM_W0 0               // 32768 : W0 chunks 2-9 (h-part) fragments
#define SM_W1 32768           // 65536 : W1 fragments (chunks 2-17 -> 0-15)
#define SM_A  98304           // 3 x 5120 : A chunk buffers (64 rows x 80B)
#define SMEM_TOTAL 113664

// ---------------- persistent device scratch ----------------
// Prepacked W fragments, fp16. Slice = 16 hidden cols x 4 gates (64 n-cols).
// Per (slice, kblk): 2 warp-n halves x 2 pairs x 32 lanes x 16B; a lane's 16B
// = B-fragments for 2 adjacent n-frags; gate = nfrag & 3 (shuffle-free epi).
__device__ __align__(16) __half g_Wp0[16 * 64 * KC0];
__device__ __align__(16) __half g_Wp1[16 * 64 * KC1];
__device__ float g_b0[G4];
__device__ float g_b1[G4];
__device__ __align__(16) __half g_xh[(size_t)TT * BB * II];  // [t][b][k]
__device__ __align__(16) __half g_h0[2][BB * HH];
__device__ __align__(16) __half g_h1[2][BB * HH];
// per-m-group barriers (16 groups of 16 CTAs), padded lines
__device__ unsigned g_bar_count[16 * 32];
__device__ unsigned g_bar_gen[16 * 32];

// ---------------- helpers ----------------
__device__ __forceinline__ uint32_t smem_u32(const void* p) {
    uint32_t a;
    asm("{ .reg .u64 t; cvta.to.shared.u64 t, %1; cvt.u32.u64 %0, t; }" : "=r"(a) : "l"(p));
    return a;
}

// ---------------- weight fragment packing (slice16, gate-per-fragment) ----------------
__device__ void packW(__half* __restrict__ Wp,
                      const float* __restrict__ wih, const float* __restrict__ whh,
                      int KIN, int KC, int KCb, int tid, int stride)
{
    const int nunits = 16 * KCb * 128;   // slices x kblks x (wn x pair x lane)
    for (int idx = tid; idx < nunits; idx += stride) {
        const int u = idx & 31;
        const int j = (idx >> 5) & 1;
        const int wn = (idx >> 6) & 1;
        int rest = idx >> 7;
        const int kb = rest % KCb;
        const int s = rest / KCb;          // 0..15
        const int col = u >> 2, kp = u & 3;
        const size_t base = (size_t)s * KCb * 1024 + (size_t)kb * 1024
                          + (wn * 2 + j) * 256 + u * 8;
        const int kbase = kb * 16 + 2 * kp;
        const int kks[4] = { kbase, kbase + 1, kbase + 8, kbase + 9 };
#pragma unroll
        for (int f = 0; f < 2; ++f) {
            const int gate = j * 2 + f;
            const int nh = wn * 8 + col;
            const int row = gate * HH + s * 16 + nh;
#pragma unroll
            for (int jj = 0; jj < 4; ++jj) {
                const int kk = kks[jj];
                const float wv = (kk < KIN) ? wih[row * KIN + kk]
                                            : whh[row * HH + (kk - KIN)];
                Wp[base + f * 4 + jj] = __float2half_rn(wv);
            }
        }
    }
}

__global__ void pack_init(const float* __restrict__ x,
                          const float* __restrict__ w_ih0, const float* __restrict__ w_hh0,
                          const float* __restrict__ b_ih0, const float* __restrict__ b_hh0,
                          const float* __restrict__ w_ih1, const float* __restrict__ w_hh1,
                          const float* __restrict__ b_ih1, const float* __restrict__ b_hh1)
{
    const int tid = blockIdx.x * blockDim.x + threadIdx.x;
    const int stride = gridDim.x * blockDim.x;

    packW(g_Wp0, w_ih0, w_hh0, II, KC0, KB0, tid, stride);
    packW(g_Wp1, w_ih1, w_hh1, HH, KC1, KB1, tid, stride);

    for (int idx = tid; idx < G4; idx += stride) {
        g_b0[idx] = b_ih0[idx] + b_hh0[idx];
        g_b1[idx] = b_ih1[idx] + b_hh1[idx];
    }
    for (size_t idx = tid; idx < (size_t)TT * BB * II; idx += stride) {
        const int k = idx % II;
        const int b = (idx / II) % BB;
        const int t = idx / ((size_t)II * BB);
        g_xh[idx] = __float2half_rn(x[((size_t)b * TT + t) * II + k]);
    }
    const __half z = __float2half_rn(0.f);
    for (int idx = tid; idx < BB * HH; idx += stride) {
        g_h0[0][idx] = z;
        g_h1[0][idx] = z;
    }
    for (int idx = tid; idx < 16 * 32; idx += stride) {
        g_bar_count[idx] = 0;
        g_bar_gen[idx] = 0;
    }
}

// ---------------- per-m-group barrier (16 CTAs) ----------------
__device__ __forceinline__ void group_sync(int grp)
{
    __threadfence();
    __syncthreads();
    if (threadIdx.x == 0) {
        volatile unsigned* genp = &g_bar_gen[grp * 32];
        const unsigned gen = *genp;
        if (atomicAdd(&g_bar_count[grp * 32], 1u) == 15u) {
            *(volatile unsigned*)&g_bar_count[grp * 32] = 0u;
            __threadfence();
            *genp = gen + 1u;
        } else {
            while (*genp == gen) {}
        }
    }
    __syncthreads();
}

// ---------------- mma wrapper ----------------
__device__ __forceinline__ void mma16816(float* d,
                                         uint32_t a0, uint32_t a1, uint32_t a2, uint32_t a3,
                                         uint32_t b0, uint32_t b1)
{
    asm volatile("mma.sync.aligned.m16n8k16.row.col.f32.f16.f16.f32 "
                 "{%0,%1,%2,%3}, {%4,%5,%6,%7}, {%8,%9}, {%0,%1,%2,%3};\n"
                 : "+f"(d[0]), "+f"(d[1]), "+f"(d[2]), "+f"(d[3])
                 : "r"(a0), "r"(a1), "r"(a2), "r"(a3), "r"(b0), "r"(b1));
}

__device__ __forceinline__ float sigm(float z) { return 1.f / (1.f + __expf(-z)); }
__device__ __forceinline__ float tanh_fast(float z) { return 2.f / (1.f + __expf(-2.f * z)) - 1.f; }

// chunk source: c 0-1 -> x(p); c 2-9 -> h0(p-1); c 10-17 -> h1(p-2)
__device__ __forceinline__ uint4 load_chunk(int c, int p, int mg, int lq)
{
    const __half* src;
    int str, koff;
    if (c < 2)       { src = g_xh + (size_t)p * BB * II; str = II; koff = c * 32; }
    else if (c < 10) { src = g_h0[p & 1];        str = HH; koff = (c - 2) * 32; }
    else             { src = g_h1[(p - 1) & 1];  str = HH; koff = (c - 10) * 32; }
    return *(const uint4*)(src + (size_t)mg * str + koff + lq * 8);
}

// ---------------- one chunk of fused GEMM (slice16 strides) ----------------
__device__ __forceinline__ void compute_chunk(
    uint32_t aAddr, const char* w0p, const char* w1p,
    float (*acc0)[4], float (*acc1)[4], bool l0, bool l1)
{
#pragma unroll
    for (int ks = 0; ks < 2; ++ks) {
        uint32_t a0r, a1r, a2r, a3r;
        asm volatile("ldmatrix.sync.aligned.m8n8.x4.shared.b16 {%0,%1,%2,%3}, [%4];"
                     : "=r"(a0r), "=r"(a1r), "=r"(a2r), "=r"(a3r)
                     : "r"(aAddr + ks * 32));
        if (l0) {
            const uint4 w0 = *(const uint4*)(w0p + ks * 2048);
            const uint4 w1 = *(const uint4*)(w0p + ks * 2048 + 512);
            mma16816(acc0[0], a0r, a1r, a2r, a3r, w0.x, w0.y);
            mma16816(acc0[1], a0r, a1r, a2r, a3r, w0.z, w0.w);
            mma16816(acc0[2], a0r, a1r, a2r, a3r, w1.x, w1.y);
            mma16816(acc0[3], a0r, a1r, a2r, a3r, w1.z, w1.w);
        }
        if (l1) {
            const uint4 w0 = *(const uint4*)(w1p + ks * 2048);
            const uint4 w1 = *(const uint4*)(w1p + ks * 2048 + 512);
            mma16816(acc1[0], a0r, a1r, a2r, a3r, w0.x, w0.y);
            mma16816(acc1[1], a0r, a1r, a2r, a3r, w0.z, w0.w);
            mma16816(acc1[2], a0r, a1r, a2r, a3r, w1.x, w1.y);
            mma16816(acc1[3], a0r, a1r, a2r, a3r, w1.z, w1.w);
        }
    }
}

// ---------------- shuffle-free cell epilogue ----------------
__device__ __forceinline__ void cell_epilogue(
    float (*acc)[4], float* __restrict__ creg,
    const float* bi, const float* bf, const float* bg, const float* bo,
    __half* __restrict__ outh, int row0, int n0)
{
#pragma unroll
    for (int half = 0; half < 2; ++half) {
        __half hv[2];
#pragma unroll
        for (int q = 0; q < 2; ++q) {
            const int j = half * 2 + q;
            const float ig = sigm(acc[0][j] + bi[q]);
            const float fg = sigm(acc[1][j] + bf[q]);
            const float gg = tanh_fast(acc[2][j] + bg[q]);
            const float og = sigm(acc[3][j] + bo[q]);
            const float cn = fg * creg[j] + ig * gg;
            creg[j] = cn;
            hv[q] = __float2half_rn(og * tanh_fast(cn));
        }
        *(uint32_t*)&outh[(size_t)(row0 + half * 8) * HH + n0] = *(const uint32_t*)hv;
    }
}

// ---------------- persistent fused LSTM (2 CTAs/SM) ----------------
// Phase p: layer0 t=p (p<TT) + layer1 t=p-1 (p>0) in one merged GEMM pass.
// h(t) in buf[(t+1)&1]; h(-1)=zeros in buf[0]. Cell state in registers.
__global__ __launch_bounds__(256, 2) void lstm_persistent()
{
    extern __shared__ __align__(128) char smc[];
    const int tid = threadIdx.x;
    const int lane = tid & 31;
    const int w = tid >> 5;      // 0..7
    const int wm = w & 3;        // m-frag block
    const int wn = w >> 2;       // 0/1: 8-hidden-col half
    const int mwb = wm * 16;
    const int b = blockIdx.x;
    const int m0 = (b & 15) * 64;
    const int s = b >> 4;        // slice 0..15 (16 hidden cols)
    const int grp = b & 15;
    const int lrow = tid >> 2;   // A-loader row 0..63
    const int lq = tid & 3;      // A-loader 16B unit
    const int mg = m0 + lrow;

    // ---- prologue: W slice (h-part of W0, all of W1) to SMEM; biases to regs ----
    {
        const uint4* w0s = (const uint4*)((const char*)g_Wp0 + (size_t)s * (KB0 * 2048) + 8192);
        uint4* w0d = (uint4*)(smc + SM_W0);
        for (int i = tid; i < 32768 / 16; i += 256) w0d[i] = w0s[i];
        const uint4* w1s = (const uint4*)((const char*)g_Wp1 + (size_t)s * (KB1 * 2048));
        uint4* w1d = (uint4*)(smc + SM_W1);
        for (int i = tid; i < 65536 / 16; i += 256) w1d[i] = w1s[i];
    }
    const int n0 = s * 16 + wn * 8 + 2 * (lane & 3);
    const int row0 = m0 + mwb + (lane >> 2);
    float b0i[2] = { g_b0[n0], g_b0[n0 + 1] };
    float b0f[2] = { g_b0[HH + n0], g_b0[HH + n0 + 1] };
    float b0g[2] = { g_b0[2 * HH + n0], g_b0[2 * HH + n0 + 1] };
    float b0o[2] = { g_b0[3 * HH + n0], g_b0[3 * HH + n0 + 1] };
    float b1i[2] = { g_b1[n0], g_b1[n0 + 1] };
    float b1f[2] = { g_b1[HH + n0], g_b1[HH + n0 + 1] };
    float b1g[2] = { g_b1[2 * HH + n0], g_b1[2 * HH + n0 + 1] };
    float b1o[2] = { g_b1[3 * HH + n0], g_b1[3 * HH + n0 + 1] };
    __syncthreads();

    // ldmatrix per-lane base address (buffer 0, ks 0)
    const uint32_t aU = smem_u32(smc) + SM_A + (mwb + (lane & 15)) * 80 + ((lane >> 4) << 4);
    const char* w0gbase = (const char*)g_Wp0 + (size_t)s * (KB0 * 2048) + wn * 1024 + lane * 16;
    const char* w0sbase = smc + SM_W0 + wn * 1024 + lane * 16;
    const char* w1sbase = smc + SM_W1 + wn * 1024 + lane * 16;

    float c0reg[4] = {0.f, 0.f, 0.f, 0.f};
    float c1reg[4] = {0.f, 0.f, 0.f, 0.f};

    for (int p = 0; p <= TT; ++p) {
        const bool do0 = (p < TT);
        const bool do1 = (p > 0);
        const int cstart = do0 ? 0 : 2;
        const int cend = do1 ? 18 : 10;

        float acc0[4][4], acc1[4][4];
#pragma unroll
        for (int nb = 0; nb < 4; ++nb)
#pragma unroll
            for (int j = 0; j < 4; ++j) { acc0[nb][j] = 0.f; acc1[nb][j] = 0.f; }

        // ---- 3-buffer rotation, distance-2 register prefetch ----
        uint4 ph0 = load_chunk(cstart, p, mg, lq);
        uint4 ph1 = (cstart + 1 < cend) ? load_chunk(cstart + 1, p, mg, lq) : ph0;
        for (int c = cstart; c < cend; ++c) {
            *(uint4*)(smc + SM_A + (c % 3) * 5120 + lrow * 80 + lq * 16) = ph0;
            ph0 = ph1;
            if (c + 2 < cend) ph1 = load_chunk(c + 2, p, mg, lq);
            __syncthreads();
            const char* w0p = (c < 2) ? (w0gbase + c * 4096)
                                      : (w0sbase + (c - 2) * 4096);
            const char* w1p = w1sbase + (c >= 2 ? (c - 2) * 4096 : 0);
            compute_chunk(aU + (c % 3) * 5120, w0p, w1p,
                          acc0, acc1, do0 && c < 10, do1 && c >= 2);
        }

        if (do0)
            cell_epilogue(acc0, c0reg, b0i, b0f, b0g, b0o,
                          g_h0[(p + 1) & 1], row0, n0);
        if (do1)
            cell_epilogue(acc1, c1reg, b1i, b1f, b1g, b1o,
                          g_h1[p & 1], row0, n0);

        group_sync(grp);
    }
}

// ---------------- final FC (O=1) ----------------
__global__ void fc_kernel(const float* __restrict__ fc_w, const float* __restrict__ fc_b,
                          float* __restrict__ out)
{
    const __half* h = g_h1[TT & 1];
    const int warp = (blockIdx.x * blockDim.x + threadIdx.x) >> 5;
    const int lane = threadIdx.x & 31;
    if (warp >= BB) return;
    float sum = 0.f;
    for (int k = lane; k < HH; k += 32)
        sum += __half2float(h[warp * HH + k]) * fc_w[k];
#pragma unroll
    for (int off = 16; off; off >>= 1) sum += __shfl_xor_sync(0xffffffffu, sum, off);
    if (lane == 0) out[warp] = sum + fc_b[0];
}

// ---------------- launch ----------------
extern "C" void kernel_launch(void* const* d_in, const int* in_sizes, int n_in,
                              void* d_out, int out_size)
{
    const float* x     = (const float*)d_in[0];
    const float* w_ih0 = (const float*)d_in[1];
    const float* w_hh0 = (const float*)d_in[2];
    const float* b_ih0 = (const float*)d_in[3];
    const float* b_hh0 = (const float*)d_in[4];
    const float* w_ih1 = (const float*)d_in[5];
    const float* w_hh1 = (const float*)d_in[6];
    const float* b_ih1 = (const float*)d_in[7];
    const float* b_hh1 = (const float*)d_in[8];
    const float* fc_w  = (const float*)d_in[9];
    const float* fc_b  = (const float*)d_in[10];
    float* out = (float*)d_out;

    cudaFuncSetAttribute(lstm_persistent,
                         cudaFuncAttributeMaxDynamicSharedMemorySize, SMEM_TOTAL);

    pack_init<<<2048, 256>>>(x, w_ih0, w_hh0, b_ih0, b_hh0,
                             w_ih1, w_hh1, b_ih1, b_hh1);
    lstm_persistent<<<NBLK, 256, SMEM_TOTAL>>>();
    fc_kernel<<<BB * 32 / 256, 256>>>(fc_w, fc_b, out);
}

// round 16
// speedup vs baseline: 1.2157x; 1.2157x over previous
#include <cuda_runtime.h>
#include <cuda_fp16.h>
#include <cstddef>
#include <cstdint>

#define BB 1024   // batch
#define TT 512    // time steps
#define II 64     // input dim
#define HH 256    // hidden dim
#define G4 1024   // 4*H
#define NBLK 128  // 16 m-tiles x 8 slices
#define KC0 (II + HH)    // 320
#define KC1 (HH + HH)    // 512
#define KB0 (KC0 / 16)   // 20
#define KB1 (KC1 / 16)   // 32

// ---- smem layout (bytes) ----
#define SM_W0 0               // 65536  : W0 chunks 2-9 (h-part) fragments
#define SM_W1 65536           // 131072 : W1 fragments (chunks 2-17 -> 0-15)
#define SM_A  196608          // 6 x 5120 : A chunk buffers (64 rows x 80B)
#define SMEM_TOTAL 227328

// ---------------- persistent device scratch ----------------
// Prepacked W fragments, fp16. Per (slice, kblk): 4 warp-n quarters x 2 pairs
// x 32 lanes x 16B. Within a warp the 4 n-fragments are the 4 GATES of the
// warp's 8 hidden cols (gate = nfrag & 3) -> epilogue needs no shuffles.
__device__ __align__(16) __half g_Wp0[8 * 128 * KC0];
__device__ __align__(16) __half g_Wp1[8 * 128 * KC1];
__device__ float g_b0[G4];
__device__ float g_b1[G4];
__device__ __align__(16) __half g_xh[(size_t)TT * BB * II];  // [t][b][k]
__device__ __align__(16) __half g_h0[2][BB * HH];
__device__ __align__(16) __half g_h1[2][BB * HH];
// per-m-group barriers (16 groups of 8 CTAs), padded lines
__device__ unsigned g_bar_count[16 * 32];
__device__ unsigned g_bar_gen[16 * 32];

// ---------------- helpers ----------------
__device__ __forceinline__ uint32_t smem_u32(const void* p) {
    uint32_t a;
    asm("{ .reg .u64 t; cvta.to.shared.u64 t, %1; cvt.u32.u64 %0, t; }" : "=r"(a) : "l"(p));
    return a;
}

// ---------------- weight fragment packing (gate-per-fragment) ----------------
__device__ void packW(__half* __restrict__ Wp,
                      const float* __restrict__ wih, const float* __restrict__ whh,
                      int KIN, int KC, int KCb, int tid, int stride)
{
    const int nunits = 8 * KCb * 4 * 2 * 32;   // slices x kblks x wn x pair x lane
    for (int idx = tid; idx < nunits; idx += stride) {
        const int u = idx & 31;
        const int j = (idx >> 5) & 1;
        const int wn = (idx >> 6) & 3;
        int rest = idx >> 8;
        const int kb = rest % KCb;
        const int s = rest / KCb;
        const int col = u >> 2, kp = u & 3;
        const size_t base = (size_t)s * KC * 128 + (size_t)kb * 2048
                          + (wn * 2 + j) * 256 + u * 8;
        const int kbase = kb * 16 + 2 * kp;
        const int kks[4] = { kbase, kbase + 1, kbase + 8, kbase + 9 };
#pragma unroll
        for (int f = 0; f < 2; ++f) {
            const int nfrag = wn * 4 + j * 2 + f;
            const int gate = nfrag & 3;                 // gate-per-fragment
            const int nh = (nfrag >> 2) * 8 + col;      // hidden col within slice
            const int row = gate * HH + s * 32 + nh;
#pragma unroll
            for (int jj = 0; jj < 4; ++jj) {
                const int kk = kks[jj];
                const float wv = (kk < KIN) ? wih[row * KIN + kk]
                                            : whh[row * HH + (kk - KIN)];
                Wp[base + f * 4 + jj] = __float2half_rn(wv);
            }
        }
    }
}

__global__ void pack_init(const float* __restrict__ x,
                          const float* __restrict__ w_ih0, const float* __restrict__ w_hh0,
                          const float* __restrict__ b_ih0, const float* __restrict__ b_hh0,
                          const float* __restrict__ w_ih1, const float* __restrict__ w_hh1,
                          const float* __restrict__ b_ih1, const float* __restrict__ b_hh1)
{
    const int tid = blockIdx.x * blockDim.x + threadIdx.x;
    const int stride = gridDim.x * blockDim.x;

    packW(g_Wp0, w_ih0, w_hh0, II, KC0, KB0, tid, stride);
    packW(g_Wp1, w_ih1, w_hh1, HH, KC1, KB1, tid, stride);

    for (int idx = tid; idx < G4; idx += stride) {
        g_b0[idx] = b_ih0[idx] + b_hh0[idx];
        g_b1[idx] = b_ih1[idx] + b_hh1[idx];
    }
    for (size_t idx = tid; idx < (size_t)TT * BB * II; idx += stride) {
        const int k = idx % II;
        const int b = (idx / II) % BB;
        const int t = idx / ((size_t)II * BB);
        g_xh[idx] = __float2half_rn(x[((size_t)b * TT + t) * II + k]);
    }
    const __half z = __float2half_rn(0.f);
    for (int idx = tid; idx < BB * HH; idx += stride) {
        g_h0[0][idx] = z;
        g_h1[0][idx] = z;
    }
    for (int idx = tid; idx < 16 * 32; idx += stride) {
        g_bar_count[idx] = 0;
        g_bar_gen[idx] = 0;
    }
}

// ---------------- per-m-group barrier (8 CTAs) ----------------
__device__ __forceinline__ void group_sync(int grp)
{
    __threadfence();
    __syncthreads();
    if (threadIdx.x == 0) {
        volatile unsigned* genp = &g_bar_gen[grp * 32];
        const unsigned gen = *genp;
        if (atomicAdd(&g_bar_count[grp * 32], 1u) == 7u) {
            *(volatile unsigned*)&g_bar_count[grp * 32] = 0u;
            __threadfence();
            *genp = gen + 1u;
        } else {
            while (*genp == gen) {}
        }
    }
    __syncthreads();
}

// ---------------- mma wrapper ----------------
__device__ __forceinline__ void mma16816(float* d,
                                         uint32_t a0, uint32_t a1, uint32_t a2, uint32_t a3,
                                         uint32_t b0, uint32_t b1)
{
    asm volatile("mma.sync.aligned.m16n8k16.row.col.f32.f16.f16.f32 "
                 "{%0,%1,%2,%3}, {%4,%5,%6,%7}, {%8,%9}, {%0,%1,%2,%3};\n"
                 : "+f"(d[0]), "+f"(d[1]), "+f"(d[2]), "+f"(d[3])
                 : "r"(a0), "r"(a1), "r"(a2), "r"(a3), "r"(b0), "r"(b1));
}

__device__ __forceinline__ float sigm(float z) { return 1.f / (1.f + __expf(-z)); }
__device__ __forceinline__ float tanh_fast(float z) { return 2.f / (1.f + __expf(-2.f * z)) - 1.f; }

// chunk source: c 0-1 -> x(p); c 2-9 -> h0(p-1); c 10-17 -> h1(p-2)
__device__ __forceinline__ uint2 load_chunk(int c, int p, int mg, int lq)
{
    const __half* src;
    int str, koff;
    if (c < 2)       { src = g_xh + (size_t)p * BB * II; str = II; koff = c * 32; }
    else if (c < 10) { src = g_h0[p & 1];        str = HH; koff = (c - 2) * 32; }
    else             { src = g_h1[(p - 1) & 1];  str = HH; koff = (c - 10) * 32; }
    return *(const uint2*)(src + (size_t)mg * str + koff + lq * 4);
}

// ---------------- one chunk of fused GEMM ----------------
__device__ __forceinline__ void compute_chunk(
    uint32_t aAddr, const char* w0p, const char* w1p,
    float (*acc0)[4], float (*acc1)[4], bool l0, bool l1)
{
#pragma unroll
    for (int ks = 0; ks < 2; ++ks) {
        uint32_t a0r, a1r, a2r, a3r;
        asm volatile("ldmatrix.sync.aligned.m8n8.x4.shared.b16 {%0,%1,%2,%3}, [%4];"
                     : "=r"(a0r), "=r"(a1r), "=r"(a2r), "=r"(a3r)
                     : "r"(aAddr + ks * 32));
        if (l0) {
            const uint4 w0 = *(const uint4*)(w0p + ks * 4096);
            const uint4 w1 = *(const uint4*)(w0p + ks * 4096 + 512);
            mma16816(acc0[0], a0r, a1r, a2r, a3r, w0.x, w0.y);
            mma16816(acc0[1], a0r, a1r, a2r, a3r, w0.z, w0.w);
            mma16816(acc0[2], a0r, a1r, a2r, a3r, w1.x, w1.y);
            mma16816(acc0[3], a0r, a1r, a2r, a3r, w1.z, w1.w);
        }
        if (l1) {
            const uint4 w0 = *(const uint4*)(w1p + ks * 4096);
            const uint4 w1 = *(const uint4*)(w1p + ks * 4096 + 512);
            mma16816(acc1[0], a0r, a1r, a2r, a3r, w0.x, w0.y);
            mma16816(acc1[1], a0r, a1r, a2r, a3r, w0.z, w0.w);
            mma16816(acc1[2], a0r, a1r, a2r, a3r, w1.x, w1.y);
            mma16816(acc1[3], a0r, a1r, a2r, a3r, w1.z, w1.w);
        }
    }
}

// ---------------- shuffle-free cell epilogue ----------------
// acc[g][j]: gate g, cell j; j=0,1 -> (row0, n0/n0+1); j=2,3 -> (row0+8, ...)
__device__ __forceinline__ void cell_epilogue(
    float (*acc)[4], float* __restrict__ creg,
    const float* bi, const float* bf, const float* bg, const float* bo,
    __half* __restrict__ outh, int row0, int n0)
{
#pragma unroll
    for (int half = 0; half < 2; ++half) {
        __half hv[2];
#pragma unroll
        for (int q = 0; q < 2; ++q) {
            const int j = half * 2 + q;
            const float ig = sigm(acc[0][j] + bi[q]);
            const float fg = sigm(acc[1][j] + bf[q]);
            const float gg = tanh_fast(acc[2][j] + bg[q]);
            const float og = sigm(acc[3][j] + bo[q]);
            const float cn = fg * creg[j] + ig * gg;
            creg[j] = cn;
            hv[q] = __float2half_rn(og * tanh_fast(cn));
        }
        *(uint32_t*)&outh[(size_t)(row0 + half * 8) * HH + n0] = *(const uint32_t*)hv;
    }
}

// ---------------- persistent fused LSTM ----------------
// Phase p: layer0 t=p (p<TT) + layer1 t=p-1 (p>0) in one merged GEMM pass.
// h(t) in buf[(t+1)&1]; h(-1)=zeros in buf[0]. Cell state in registers.
__global__ __launch_bounds__(512, 1) void lstm_persistent()
{
    extern __shared__ __align__(128) char smc[];
    const int tid = threadIdx.x;
    const int lane = tid & 31;
    const int w = tid >> 5;      // 0..15
    const int wm = w & 3;
    const int wn = w >> 2;       // 8-hidden-col quarter
    const int mwb = wm * 16;
    const int b = blockIdx.x;
    const int m0 = (b & 15) * 64;
    const int s = b >> 4;        // slice 0..7
    const int grp = b & 15;
    const int lrow = tid >> 3;   // A-loader row 0..63
    const int lq = tid & 7;      // A-loader 8B unit
    const int mg = m0 + lrow;

    // ---- prologue: W slice (h-part of W0, all of W1) to SMEM; biases to regs ----
    {
        const uint4* w0s = (const uint4*)((const char*)g_Wp0 + (size_t)s * 81920 + 16384);
        uint4* w0d = (uint4*)(smc + SM_W0);
        for (int i = tid; i < 65536 / 16; i += 512) w0d[i] = w0s[i];
        const uint4* w1s = (const uint4*)((const char*)g_Wp1 + (size_t)s * 131072);
        uint4* w1d = (uint4*)(smc + SM_W1);
        for (int i = tid; i < 131072 / 16; i += 512) w1d[i] = w1s[i];
    }
    const int n0 = s * 32 + wn * 8 + 2 * (lane & 3);
    const int row0 = m0 + mwb + (lane >> 2);
    float b0i[2] = { g_b0[n0], g_b0[n0 + 1] };
    float b0f[2] = { g_b0[HH + n0], g_b0[HH + n0 + 1] };
    float b0g[2] = { g_b0[2 * HH + n0], g_b0[2 * HH + n0 + 1] };
    float b0o[2] = { g_b0[3 * HH + n0], g_b0[3 * HH + n0 + 1] };
    float b1i[2] = { g_b1[n0], g_b1[n0 + 1] };
    float b1f[2] = { g_b1[HH + n0], g_b1[HH + n0 + 1] };
    float b1g[2] = { g_b1[2 * HH + n0], g_b1[2 * HH + n0 + 1] };
    float b1o[2] = { g_b1[3 * HH + n0], g_b1[3 * HH + n0 + 1] };
    __syncthreads();

    // ldmatrix per-lane base address (buffer 0, ks 0)
    const uint32_t aU = smem_u32(smc) + SM_A + (mwb + (lane & 15)) * 80 + ((lane >> 4) << 4);
    const char* w0gbase = (const char*)g_Wp0 + (size_t)s * 81920 + wn * 1024 + lane * 16;
    const char* w0sbase = smc + SM_W0 + wn * 1024 + lane * 16;
    const char* w1sbase = smc + SM_W1 + wn * 1024 + lane * 16;

    float c0reg[4] = {0.f, 0.f, 0.f, 0.f};
    float c1reg[4] = {0.f, 0.f, 0.f, 0.f};

    for (int p = 0; p <= TT; ++p) {
        const bool do0 = (p < TT);
        const bool do1 = (p > 0);

        float acc0[4][4], acc1[4][4];
#pragma unroll
        for (int nb = 0; nb < 4; ++nb)
#pragma unroll
            for (int j = 0; j < 4; ++j) { acc0[nb][j] = 0.f; acc1[nb][j] = 0.f; }

        if (do0 && do1) {
            // ---- steady state: 18 chunks as 6 triples, 1 sync per triple ----
            uint2 ra0 = load_chunk(0, p, mg, lq);
            uint2 ra1 = load_chunk(1, p, mg, lq);
            uint2 ra2 = load_chunk(2, p, mg, lq);
#pragma unroll
            for (int g = 0; g < 6; ++g) {
                const int base = (g & 1) * 3;
                *(uint2*)(smc + SM_A + (base + 0) * 5120 + lrow * 80 + lq * 8) = ra0;
                *(uint2*)(smc + SM_A + (base + 1) * 5120 + lrow * 80 + lq * 8) = ra1;
                *(uint2*)(smc + SM_A + (base + 2) * 5120 + lrow * 80 + lq * 8) = ra2;
                if (g < 5) {
                    ra0 = load_chunk(3 * g + 3, p, mg, lq);
                    ra1 = load_chunk(3 * g + 4, p, mg, lq);
                    ra2 = load_chunk(3 * g + 5, p, mg, lq);
                }
                __syncthreads();
#pragma unroll
                for (int q = 0; q < 3; ++q) {
                    const int c = 3 * g + q;
                    const char* w0p = (c < 2) ? (w0gbase + c * 8192)
                                              : (w0sbase + (c - 2) * 8192);
                    const char* w1p = w1sbase + (c >= 2 ? (c - 2) * 8192 : 0);
                    compute_chunk(aU + (base + q) * 5120, w0p, w1p,
                                  acc0, acc1, c < 10, c >= 2);
                }
            }
        } else {
            // ---- boundary phases (p==0 or p==TT): generic 2-buffer path ----
            const int cstart = do0 ? 0 : 2;
            const int cend = do1 ? 18 : 10;
            uint2 ph = load_chunk(cstart, p, mg, lq);
            *(uint2*)(smc + SM_A + (cstart & 1) * 5120 + lrow * 80 + lq * 8) = ph;
            if (cstart + 1 < cend) ph = load_chunk(cstart + 1, p, mg, lq);
            __syncthreads();
            for (int c = cstart; c < cend; ++c) {
                if (c + 1 < cend)
                    *(uint2*)(smc + SM_A + ((c + 1) & 1) * 5120 + lrow * 80 + lq * 8) = ph;
                if (c + 2 < cend) ph = load_chunk(c + 2, p, mg, lq);
                const char* w0p = (c < 2) ? (w0gbase + c * 8192)
                                          : (w0sbase + (c - 2) * 8192);
                const char* w1p = w1sbase + (c >= 2 ? (c - 2) * 8192 : 0);
                compute_chunk(aU + (c & 1) * 5120, w0p, w1p,
                              acc0, acc1, do0 && c < 10, do1 && c >= 2);
                __syncthreads();
            }
        }

        if (do0)
            cell_epilogue(acc0, c0reg, b0i, b0f, b0g, b0o,
                          g_h0[(p + 1) & 1], row0, n0);
        if (do1)
            cell_epilogue(acc1, c1reg, b1i, b1f, b1g, b1o,
                          g_h1[p & 1], row0, n0);

        group_sync(grp);
    }
}

// ---------------- final FC (O=1) ----------------
__global__ void fc_kernel(const float* __restrict__ fc_w, const float* __restrict__ fc_b,
                          float* __restrict__ out)
{
    const __half* h = g_h1[TT & 1];
    const int warp = (blockIdx.x * blockDim.x + threadIdx.x) >> 5;
    const int lane = threadIdx.x & 31;
    if (warp >= BB) return;
    float sum = 0.f;
    for (int k = lane; k < HH; k += 32)
        sum += __half2float(h[warp * HH + k]) * fc_w[k];
#pragma unroll
    for (int off = 16; off; off >>= 1) sum += __shfl_xor_sync(0xffffffffu, sum, off);
    if (lane == 0) out[warp] = sum + fc_b[0];
}

// ---------------- launch ----------------
extern "C" void kernel_launch(void* const* d_in, const int* in_sizes, int n_in,
                              void* d_out, int out_size)
{
    const float* x     = (const float*)d_in[0];
    const float* w_ih0 = (const float*)d_in[1];
    const float* w_hh0 = (const float*)d_in[2];
    const float* b_ih0 = (const float*)d_in[3];
    const float* b_hh0 = (const float*)d_in[4];
    const float* w_ih1 = (const float*)d_in[5];
    const float* w_hh1 = (const float*)d_in[6];
    const float* b_ih1 = (const float*)d_in[7];
    const float* b_hh1 = (const float*)d_in[8];
    const float* fc_w  = (const float*)d_in[9];
    const float* fc_b  = (const float*)d_in[10];
    float* out = (float*)d_out;

    cudaFuncSetAttribute(lstm_persistent,
                         cudaFuncAttributeMaxDynamicSharedMemorySize, SMEM_TOTAL);

    pack_init<<<2048, 256>>>(x, w_ih0, w_hh0, b_ih0, b_hh0,
                             w_ih1, w_hh1, b_ih1, b_hh1);
    lstm_persistent<<<NBLK, 512, SMEM_TOTAL>>>();
    fc_kernel<<<BB * 32 / 256, 256>>>(fc_w, fc_b, out);
}

// round 17
// speedup vs baseline: 1.5271x; 1.2561x over previous
#include <cuda_runtime.h>
#include <cuda_fp16.h>
#include <cstddef>
#include <cstdint>

#define BB 1024   // batch
#define TT 512    // time steps
#define II 64     // input dim
#define HH 256    // hidden dim
#define G4 1024   // 4*H
#define NBLK 128  // 16 m-tiles x 8 slices
#define KC0 (II + HH)    // 320
#define KC1 (HH + HH)    // 512
#define KB0 (KC0 / 16)   // 20
#define KB1 (KC1 / 16)   // 32

// ---- smem layout (bytes) ----
#define SM_W0 0               // 65536  : W0 chunks 2-9 (h-part) fragments
#define SM_W1 65536           // 131072 : W1 fragments (chunks 2-17 -> 0-15)
#define SM_A  196608          // 6 x 5120 : A chunk buffers (64 rows x 80B)
#define SMEM_TOTAL 227328

// ---------------- persistent device scratch ----------------
// Prepacked W fragments, fp16. Per (slice, kblk): 4 warp-n quarters x 2 pairs
// x 32 lanes x 16B. Within a warp the 4 n-fragments are the 4 GATES of the
// warp's 8 hidden cols (gate = nfrag & 3) -> epilogue needs no shuffles.
__device__ __align__(16) __half g_Wp0[8 * 128 * KC0];
__device__ __align__(16) __half g_Wp1[8 * 128 * KC1];
__device__ float g_b0[G4];
__device__ float g_b1[G4];
__device__ __align__(16) __half g_xh[(size_t)TT * BB * II];  // [t][b][k]
__device__ __align__(16) __half g_h0[2][BB * HH];
__device__ __align__(16) __half g_h1[2][BB * HH];
// per-m-group barriers (16 groups of 8 CTAs), padded lines
__device__ unsigned g_bar_count[16 * 32];
__device__ unsigned g_bar_gen[16 * 32];

// ---------------- helpers ----------------
__device__ __forceinline__ uint32_t smem_u32(const void* p) {
    uint32_t a;
    asm("{ .reg .u64 t; cvta.to.shared.u64 t, %1; cvt.u32.u64 %0, t; }" : "=r"(a) : "l"(p));
    return a;
}

// ---------------- weight fragment packing (gate-per-fragment) ----------------
__device__ void packW(__half* __restrict__ Wp,
                      const float* __restrict__ wih, const float* __restrict__ whh,
                      int KIN, int KC, int KCb, int tid, int stride)
{
    const int nunits = 8 * KCb * 4 * 2 * 32;   // slices x kblks x wn x pair x lane
    for (int idx = tid; idx < nunits; idx += stride) {
        const int u = idx & 31;
        const int j = (idx >> 5) & 1;
        const int wn = (idx >> 6) & 3;
        int rest = idx >> 8;
        const int kb = rest % KCb;
        const int s = rest / KCb;
        const int col = u >> 2, kp = u & 3;
        const size_t base = (size_t)s * KC * 128 + (size_t)kb * 2048
                          + (wn * 2 + j) * 256 + u * 8;
        const int kbase = kb * 16 + 2 * kp;
        const int kks[4] = { kbase, kbase + 1, kbase + 8, kbase + 9 };
#pragma unroll
        for (int f = 0; f < 2; ++f) {
            const int nfrag = wn * 4 + j * 2 + f;
            const int gate = nfrag & 3;                 // gate-per-fragment
            const int nh = (nfrag >> 2) * 8 + col;      // hidden col within slice
            const int row = gate * HH + s * 32 + nh;
#pragma unroll
            for (int jj = 0; jj < 4; ++jj) {
                const int kk = kks[jj];
                const float wv = (kk < KIN) ? wih[row * KIN + kk]
                                            : whh[row * HH + (kk - KIN)];
                Wp[base + f * 4 + jj] = __float2half_rn(wv);
            }
        }
    }
}

__global__ void pack_init(const float* __restrict__ x,
                          const float* __restrict__ w_ih0, const float* __restrict__ w_hh0,
                          const float* __restrict__ b_ih0, const float* __restrict__ b_hh0,
                          const float* __restrict__ w_ih1, const float* __restrict__ w_hh1,
                          const float* __restrict__ b_ih1, const float* __restrict__ b_hh1)
{
    const int tid = blockIdx.x * blockDim.x + threadIdx.x;
    const int stride = gridDim.x * blockDim.x;

    packW(g_Wp0, w_ih0, w_hh0, II, KC0, KB0, tid, stride);
    packW(g_Wp1, w_ih1, w_hh1, HH, KC1, KB1, tid, stride);

    for (int idx = tid; idx < G4; idx += stride) {
        g_b0[idx] = b_ih0[idx] + b_hh0[idx];
        g_b1[idx] = b_ih1[idx] + b_hh1[idx];
    }
    for (size_t idx = tid; idx < (size_t)TT * BB * II; idx += stride) {
        const int k = idx % II;
        const int b = (idx / II) % BB;
        const int t = idx / ((size_t)II * BB);
        g_xh[idx] = __float2half_rn(x[((size_t)b * TT + t) * II + k]);
    }
    const __half z = __float2half_rn(0.f);
    for (int idx = tid; idx < BB * HH; idx += stride) {
        g_h0[0][idx] = z;
        g_h1[0][idx] = z;
    }
    for (int idx = tid; idx < 16 * 32; idx += stride) {
        g_bar_count[idx] = 0;
        g_bar_gen[idx] = 0;
    }
}

// ---------------- per-m-group barrier (8 CTAs) ----------------
__device__ __forceinline__ void group_sync(int grp)
{
    __threadfence();
    __syncthreads();
    if (threadIdx.x == 0) {
        volatile unsigned* genp = &g_bar_gen[grp * 32];
        const unsigned gen = *genp;
        if (atomicAdd(&g_bar_count[grp * 32], 1u) == 7u) {
            *(volatile unsigned*)&g_bar_count[grp * 32] = 0u;
            __threadfence();
            *genp = gen + 1u;
        } else {
            while (*genp == gen) {}
        }
    }
    __syncthreads();
}

// ---------------- mma wrapper ----------------
__device__ __forceinline__ void mma16816(float* d,
                                         uint32_t a0, uint32_t a1, uint32_t a2, uint32_t a3,
                                         uint32_t b0, uint32_t b1)
{
    asm volatile("mma.sync.aligned.m16n8k16.row.col.f32.f16.f16.f32 "
                 "{%0,%1,%2,%3}, {%4,%5,%6,%7}, {%8,%9}, {%0,%1,%2,%3};\n"
                 : "+f"(d[0]), "+f"(d[1]), "+f"(d[2]), "+f"(d[3])
                 : "r"(a0), "r"(a1), "r"(a2), "r"(a3), "r"(b0), "r"(b1));
}

// ---------------- activations: single-MUFU tanh.approx ----------------
__device__ __forceinline__ float tanh_hw(float z) {
    float r;
    asm("tanh.approx.f32 %0, %1;" : "=f"(r) : "f"(z));
    return r;
}
__device__ __forceinline__ float sigm(float z) {
    return fmaf(tanh_hw(0.5f * z), 0.5f, 0.5f);
}

// chunk source: c 0-1 -> x(p); c 2-9 -> h0(p-1); c 10-17 -> h1(p-2)
__device__ __forceinline__ uint2 load_chunk(int c, int p, int mg, int lq)
{
    const __half* src;
    int str, koff;
    if (c < 2)       { src = g_xh + (size_t)p * BB * II; str = II; koff = c * 32; }
    else if (c < 10) { src = g_h0[p & 1];        str = HH; koff = (c - 2) * 32; }
    else             { src = g_h1[(p - 1) & 1];  str = HH; koff = (c - 10) * 32; }
    return *(const uint2*)(src + (size_t)mg * str + koff + lq * 4);
}

// ---------------- one chunk of fused GEMM ----------------
__device__ __forceinline__ void compute_chunk(
    uint32_t aAddr, const char* w0p, const char* w1p,
    float (*acc0)[4], float (*acc1)[4], bool l0, bool l1)
{
#pragma unroll
    for (int ks = 0; ks < 2; ++ks) {
        uint32_t a0r, a1r, a2r, a3r;
        asm volatile("ldmatrix.sync.aligned.m8n8.x4.shared.b16 {%0,%1,%2,%3}, [%4];"
                     : "=r"(a0r), "=r"(a1r), "=r"(a2r), "=r"(a3r)
                     : "r"(aAddr + ks * 32));
        if (l0) {
            const uint4 w0 = *(const uint4*)(w0p + ks * 4096);
            const uint4 w1 = *(const uint4*)(w0p + ks * 4096 + 512);
            mma16816(acc0[0], a0r, a1r, a2r, a3r, w0.x, w0.y);
            mma16816(acc0[1], a0r, a1r, a2r, a3r, w0.z, w0.w);
            mma16816(acc0[2], a0r, a1r, a2r, a3r, w1.x, w1.y);
            mma16816(acc0[3], a0r, a1r, a2r, a3r, w1.z, w1.w);
        }
        if (l1) {
            const uint4 w0 = *(const uint4*)(w1p + ks * 4096);
            const uint4 w1 = *(const uint4*)(w1p + ks * 4096 + 512);
            mma16816(acc1[0], a0r, a1r, a2r, a3r, w0.x, w0.y);
            mma16816(acc1[1], a0r, a1r, a2r, a3r, w0.z, w0.w);
            mma16816(acc1[2], a0r, a1r, a2r, a3r, w1.x, w1.y);
            mma16816(acc1[3], a0r, a1r, a2r, a3r, w1.z, w1.w);
        }
    }
}

// ---------------- shuffle-free cell epilogue ----------------
// acc[g][j]: gate g, cell j; j=0,1 -> (row0, n0/n0+1); j=2,3 -> (row0+8, ...)
__device__ __forceinline__ void cell_epilogue(
    float (*acc)[4], float* __restrict__ creg,
    const float* bi, const float* bf, const float* bg, const float* bo,
    __half* __restrict__ outh, int row0, int n0)
{
#pragma unroll
    for (int half = 0; half < 2; ++half) {
        __half hv[2];
#pragma unroll
        for (int q = 0; q < 2; ++q) {
            const int j = half * 2 + q;
            const float ig = sigm(acc[0][j] + bi[q]);
            const float fg = sigm(acc[1][j] + bf[q]);
            const float gg = tanh_hw(acc[2][j] + bg[q]);
            const float og = sigm(acc[3][j] + bo[q]);
            const float cn = fg * creg[j] + ig * gg;
            creg[j] = cn;
            hv[q] = __float2half_rn(og * tanh_hw(cn));
        }
        *(uint32_t*)&outh[(size_t)(row0 + half * 8) * HH + n0] = *(const uint32_t*)hv;
    }
}

// ---------------- persistent fused LSTM ----------------
// Phase p: layer0 t=p (p<TT) + layer1 t=p-1 (p>0) in one merged GEMM pass.
// h(t) in buf[(t+1)&1]; h(-1)=zeros in buf[0]. Cell state in registers.
__global__ __launch_bounds__(512, 1) void lstm_persistent()
{
    extern __shared__ __align__(128) char smc[];
    const int tid = threadIdx.x;
    const int lane = tid & 31;
    const int w = tid >> 5;      // 0..15
    const int wm = w & 3;
    const int wn = w >> 2;       // 8-hidden-col quarter
    const int mwb = wm * 16;
    const int b = blockIdx.x;
    const int m0 = (b & 15) * 64;
    const int s = b >> 4;        // slice 0..7
    const int grp = b & 15;
    const int lrow = tid >> 3;   // A-loader row 0..63
    const int lq = tid & 7;      // A-loader 8B unit
    const int mg = m0 + lrow;

    // ---- prologue: W slice (h-part of W0, all of W1) to SMEM; biases to regs ----
    {
        const uint4* w0s = (const uint4*)((const char*)g_Wp0 + (size_t)s * 81920 + 16384);
        uint4* w0d = (uint4*)(smc + SM_W0);
        for (int i = tid; i < 65536 / 16; i += 512) w0d[i] = w0s[i];
        const uint4* w1s = (const uint4*)((const char*)g_Wp1 + (size_t)s * 131072);
        uint4* w1d = (uint4*)(smc + SM_W1);
        for (int i = tid; i < 131072 / 16; i += 512) w1d[i] = w1s[i];
    }
    const int n0 = s * 32 + wn * 8 + 2 * (lane & 3);
    const int row0 = m0 + mwb + (lane >> 2);
    float b0i[2] = { g_b0[n0], g_b0[n0 + 1] };
    float b0f[2] = { g_b0[HH + n0], g_b0[HH + n0 + 1] };
    float b0g[2] = { g_b0[2 * HH + n0], g_b0[2 * HH + n0 + 1] };
    float b0o[2] = { g_b0[3 * HH + n0], g_b0[3 * HH + n0 + 1] };
    float b1i[2] = { g_b1[n0], g_b1[n0 + 1] };
    float b1f[2] = { g_b1[HH + n0], g_b1[HH + n0 + 1] };
    float b1g[2] = { g_b1[2 * HH + n0], g_b1[2 * HH + n0 + 1] };
    float b1o[2] = { g_b1[3 * HH + n0], g_b1[3 * HH + n0 + 1] };
    __syncthreads();

    // ldmatrix per-lane base address (buffer 0, ks 0)
    const uint32_t aU = smem_u32(smc) + SM_A + (mwb + (lane & 15)) * 80 + ((lane >> 4) << 4);
    const char* w0gbase = (const char*)g_Wp0 + (size_t)s * 81920 + wn * 1024 + lane * 16;
    const char* w0sbase = smc + SM_W0 + wn * 1024 + lane * 16;
    const char* w1sbase = smc + SM_W1 + wn * 1024 + lane * 16;

    float c0reg[4] = {0.f, 0.f, 0.f, 0.f};
    float c1reg[4] = {0.f, 0.f, 0.f, 0.f};

    for (int p = 0; p <= TT; ++p) {
        const bool do0 = (p < TT);
        const bool do1 = (p > 0);

        float acc0[4][4], acc1[4][4];
#pragma unroll
        for (int nb = 0; nb < 4; ++nb)
#pragma unroll
            for (int j = 0; j < 4; ++j) { acc0[nb][j] = 0.f; acc1[nb][j] = 0.f; }

        if (do0 && do1) {
            // ---- steady state: 18 chunks as 6 triples, 1 sync per triple ----
            uint2 ra0 = load_chunk(0, p, mg, lq);
            uint2 ra1 = load_chunk(1, p, mg, lq);
            uint2 ra2 = load_chunk(2, p, mg, lq);
#pragma unroll
            for (int g = 0; g < 6; ++g) {
                const int base = (g & 1) * 3;
                *(uint2*)(smc + SM_A + (base + 0) * 5120 + lrow * 80 + lq * 8) = ra0;
                *(uint2*)(smc + SM_A + (base + 1) * 5120 + lrow * 80 + lq * 8) = ra1;
                *(uint2*)(smc + SM_A + (base + 2) * 5120 + lrow * 80 + lq * 8) = ra2;
                if (g < 5) {
                    ra0 = load_chunk(3 * g + 3, p, mg, lq);
                    ra1 = load_chunk(3 * g + 4, p, mg, lq);
                    ra2 = load_chunk(3 * g + 5, p, mg, lq);
                }
                __syncthreads();
#pragma unroll
                for (int q = 0; q < 3; ++q) {
                    const int c = 3 * g + q;
                    const char* w0p = (c < 2) ? (w0gbase + c * 8192)
                                              : (w0sbase + (c - 2) * 8192);
                    const char* w1p = w1sbase + (c >= 2 ? (c - 2) * 8192 : 0);
                    compute_chunk(aU + (base + q) * 5120, w0p, w1p,
                                  acc0, acc1, c < 10, c >= 2);
                }
            }
        } else {
            // ---- boundary phases (p==0 or p==TT): generic 2-buffer path ----
            const int cstart = do0 ? 0 : 2;
            const int cend = do1 ? 18 : 10;
            uint2 ph = load_chunk(cstart, p, mg, lq);
            *(uint2*)(smc + SM_A + (cstart & 1) * 5120 + lrow * 80 + lq * 8) = ph;
            if (cstart + 1 < cend) ph = load_chunk(cstart + 1, p, mg, lq);
            __syncthreads();
            for (int c = cstart; c < cend; ++c) {
                if (c + 1 < cend)
                    *(uint2*)(smc + SM_A + ((c + 1) & 1) * 5120 + lrow * 80 + lq * 8) = ph;
                if (c + 2 < cend) ph = load_chunk(c + 2, p, mg, lq);
                const char* w0p = (c < 2) ? (w0gbase + c * 8192)
                                          : (w0sbase + (c - 2) * 8192);
                const char* w1p = w1sbase + (c >= 2 ? (c - 2) * 8192 : 0);
                compute_chunk(aU + (c & 1) * 5120, w0p, w1p,
                              acc0, acc1, do0 && c < 10, do1 && c >= 2);
                __syncthreads();
            }
        }

        if (do0)
            cell_epilogue(acc0, c0reg, b0i, b0f, b0g, b0o,
                          g_h0[(p + 1) & 1], row0, n0);
        if (do1)
            cell_epilogue(acc1, c1reg, b1i, b1f, b1g, b1o,
                          g_h1[p & 1], row0, n0);

        group_sync(grp);
    }
}

// ---------------- final FC (O=1) ----------------
__global__ void fc_kernel(const float* __restrict__ fc_w, const float* __restrict__ fc_b,
                          float* __restrict__ out)
{
    const __half* h = g_h1[TT & 1];
    const int warp = (blockIdx.x * blockDim.x + threadIdx.x) >> 5;
    const int lane = threadIdx.x & 31;
    if (warp >= BB) return;
    float sum = 0.f;
    for (int k = lane; k < HH; k += 32)
        sum += __half2float(h[warp * HH + k]) * fc_w[k];
#pragma unroll
    for (int off = 16; off; off >>= 1) sum += __shfl_xor_sync(0xffffffffu, sum, off);
    if (lane == 0) out[warp] = sum + fc_b[0];
}

// ---------------- launch ----------------
extern "C" void kernel_launch(void* const* d_in, const int* in_sizes, int n_in,
                              void* d_out, int out_size)
{
    const float* x     = (const float*)d_in[0];
    const float* w_ih0 = (const float*)d_in[1];
    const float* w_hh0 = (const float*)d_in[2];
    const float* b_ih0 = (const float*)d_in[3];
    const float* b_hh0 = (const float*)d_in[4];
    const float* w_ih1 = (const float*)d_in[5];
    const float* w_hh1 = (const float*)d_in[6];
    const float* b_ih1 = (const float*)d_in[7];
    const float* b_hh1 = (const float*)d_in[8];
    const float* fc_w  = (const float*)d_in[9];
    const float* fc_b  = (const float*)d_in[10];
    float* out = (float*)d_out;

    cudaFuncSetAttribute(lstm_persistent,
                         cudaFuncAttributeMaxDynamicSharedMemorySize, SMEM_TOTAL);

    pack_init<<<2048, 256>>>(x, w_ih0, w_hh0, b_ih0, b_hh0,
                             w_ih1, w_hh1, b_ih1, b_hh1);
    lstm_persistent<<<NBLK, 512, SMEM_TOTAL>>>();
    fc_kernel<<<BB * 32 / 256, 256>>>(fc_w, fc_b, out);
}